// round 7
// baseline (speedup 1.0000x reference)
#include <cuda_runtime.h>
#include <cstdint>

// Implicit-GEMM conv2d via mma.sync tf32 + ldmatrix, rs-major K ordering.
// x: [32,128,56,56] f32, W: [256,128,3,3] f32 -> out: [32,256,56,56] f32
// Pre-pass 1: W -> g_wt[oc][rs*128+ci] (tf32).  Pre-pass 2: x -> g_xt (tf32).
// Main: D[oc,pix] = sum_k' W'[oc,k'] * im2col'(x)[k',pix], k' = rs*128+ci.
// CTA 128x128, warps 2x4, warp tile 64x32, KC=16, 40KB static smem (no attr calls!).

#define NIMG   32
#define CIN    128
#define HWDIM  56
#define OCTOT  256
#define IMGPIX 3136
#define XCH    (CIN*IMGPIX)
#define KTOT   1152
#define NPIX   (NIMG*IMGPIX)
#define KC     16
#define NSTEP  (KTOT/KC)      // 72
#define TILE_N 128
#define LDT    20             // smem row stride (floats)
#define TSZ    (128*LDT)

__device__ uint32_t g_xt[NIMG * XCH];     // x in tf32 bits (51.4 MB)
__device__ uint32_t g_wt[OCTOT * KTOT];   // W reordered [oc][rs*128+ci], tf32

__device__ __forceinline__ uint32_t cvt_tf32(float f) {
    uint32_t r;
    asm("cvt.rna.tf32.f32 %0, %1;" : "=r"(r) : "f"(f));
    return r;
}
__device__ __forceinline__ void mma8(float* c, const uint32_t* a, const uint32_t* b) {
    asm volatile(
        "mma.sync.aligned.m16n8k8.row.col.f32.tf32.tf32.f32 "
        "{%0,%1,%2,%3}, {%4,%5,%6,%7}, {%8,%9}, {%0,%1,%2,%3};"
        : "+f"(c[0]), "+f"(c[1]), "+f"(c[2]), "+f"(c[3])
        : "r"(a[0]), "r"(a[1]), "r"(a[2]), "r"(a[3]), "r"(b[0]), "r"(b[1]));
}
__device__ __forceinline__ void ldsm4(uint32_t* r, uint32_t saddr) {
    asm volatile("ldmatrix.sync.aligned.m8n8.x4.shared.b16 {%0,%1,%2,%3}, [%4];"
                 : "=r"(r[0]), "=r"(r[1]), "=r"(r[2]), "=r"(r[3]) : "r"(saddr));
}

// ---------------- pre-pass kernels ----------------
__global__ void wprep_kernel(const float* __restrict__ w) {
    int i = blockIdx.x * 256 + threadIdx.x;
    if (i < OCTOT * KTOT) {
        int oc = i / KTOT;
        int kk = i - oc * KTOT;          // rs*128 + ci
        int rs = kk >> 7;
        int ci = kk & 127;
        g_wt[i] = cvt_tf32(w[oc * KTOT + ci * 9 + rs]);
    }
}
__global__ void xprep_kernel(const float* __restrict__ x) {
    int i = blockIdx.x * 256 + threadIdx.x;
    if (i < NIMG * XCH) g_xt[i] = cvt_tf32(x[i]);
}

// ---------------- main kernel ----------------
__global__ __launch_bounds__(256, 2)
void conv_mma_kernel(float* __restrict__ out)
{
    __shared__ uint32_t smem[4 * TSZ];            // A0 A1 B0 B1 = 40 KB
    uint32_t* const bufA[2] = { smem, smem + TSZ };
    uint32_t* const bufB[2] = { smem + 2 * TSZ, smem + 3 * TSZ };
    const uint32_t sb = (uint32_t)__cvta_generic_to_shared(smem);

    const int tid  = threadIdx.x;
    const int lane = tid & 31;
    const int warp = tid >> 5;
    const int wm   = warp >> 2;
    const int wn   = warp & 3;

    const int tileBase = blockIdx.x * TILE_N;
    const int ocBase   = blockIdx.y * 128;

    // ldmatrix per-thread invariant offsets (bytes)
    const int arow = wm * 64 + ((lane >> 3) & 1) * 8 + (lane & 7);
    const int acol = (lane >> 4) * 4;
    const uint32_t aoff = (uint32_t)(arow * LDT + acol) * 4u;
    const int brow = wn * 32 + (lane >> 4) * 8 + (lane & 7);
    const int bcol = ((lane >> 3) & 1) * 4;
    const uint32_t boff = (uint32_t)(brow * LDT + bcol) * 4u;

    // B-load mapping: thread -> (local pixel, k-half)
    const int pl = tid & 127;
    const int kh = tid >> 7;                      // 0/1 -> ci offset 8*kh
    const int P  = tileBase + pl;
    const int n_img = P / IMGPIX;
    const int q  = P - n_img * IMGPIX;
    const int hh = q / HWDIM;
    const int ww = q - hh * HWDIM;
    const uint32_t* xb = g_xt + (size_t)n_img * XCH + hh * HWDIM + ww;

    float acc[4][4][4];
#pragma unroll
    for (int i = 0; i < 4; i++)
#pragma unroll
        for (int j = 0; j < 4; j++)
#pragma unroll
            for (int k2 = 0; k2 < 4; k2++) acc[i][j][k2] = 0.f;

    // ---- stage loader: stage s covers rs = s>>3, ci = (s&7)*16 .. +15 ----
    auto load_stage = [&](uint32_t* Ad, uint32_t* Bd, int s) {
        const int rs = s >> 3;
        const int cib = (s & 7) * 16;
        // A: 128 oc x 16 ci, coalesced LDG.128 from reordered W'
        const uint32_t* wrow = g_wt + rs * 128 + cib;
#pragma unroll
        for (int i = 0; i < 2; i++) {
            int item = i * 256 + tid;
            int oc = item >> 2;
            int kq = item & 3;
            uint4 v = *(const uint4*)(wrow + (size_t)(ocBase + oc) * KTOT + kq * 4);
            uint32_t* dst = Ad + oc * LDT + kq * 4;
            dst[0] = v.x; dst[1] = v.y; dst[2] = v.z; dst[3] = v.w;
        }
        // B: per-stage fixed (dr,ds); 8 predicated coalesced LDG.32
        const int r3 = rs / 3;
        const int dr = r3 - 1;
        const int ds = rs - r3 * 3 - 1;
        const bool in = ((unsigned)(hh + dr) < HWDIM) && ((unsigned)(ww + ds) < HWDIM);
        const uint32_t* xp = xb + (cib + kh * 8) * IMGPIX + dr * HWDIM + ds;
        uint32_t* bdst = Bd + pl * LDT + kh * 8;
#pragma unroll
        for (int j = 0; j < 8; j++)
            bdst[j] = in ? xp[j * IMGPIX] : 0u;
    };

    load_stage(bufA[0], bufB[0], 0);
    __syncthreads();

    for (int s = 0; s < NSTEP; s++) {
        const int cur = s & 1;
        if (s + 1 < NSTEP)
            load_stage(bufA[cur ^ 1], bufB[cur ^ 1], s + 1);

        const uint32_t Abase = sb + (uint32_t)(cur * TSZ) * 4u + aoff;
        const uint32_t Bbase = sb + (uint32_t)((2 + cur) * TSZ) * 4u + boff;
#pragma unroll
        for (int ks = 0; ks < 2; ks++) {
            uint32_t a[4][4], b[2][4];
#pragma unroll
            for (int mt = 0; mt < 4; mt++)
                ldsm4(a[mt], Abase + (uint32_t)((mt * 16 * LDT + ks * 8) * 4));
#pragma unroll
            for (int np = 0; np < 2; np++)
                ldsm4(b[np], Bbase + (uint32_t)((np * 16 * LDT + ks * 8) * 4));
#pragma unroll
            for (int mt = 0; mt < 4; mt++)
#pragma unroll
                for (int nt = 0; nt < 4; nt++)
                    mma8(acc[mt][nt], a[mt], &b[nt >> 1][(nt & 1) * 2]);
        }
        __syncthreads();
    }

    // ---- epilogue: direct STG.64 (c0,c1 adjacent pixels) ----
    const int g   = lane >> 2;
    const int tig = lane & 3;
#pragma unroll
    for (int nt = 0; nt < 4; nt++) {
        int Pp = tileBase + wn * 32 + nt * 8 + 2 * tig;
        int n2 = Pp / IMGPIX;
        int rm = Pp - n2 * IMGPIX;
        float* baseo = out + ((size_t)n2 * OCTOT + ocBase) * IMGPIX + rm;
#pragma unroll
        for (int mt = 0; mt < 4; mt++) {
            int oc0 = wm * 64 + mt * 16 + g;
            float2 v0 = make_float2(acc[mt][nt][0], acc[mt][nt][1]);
            float2 v1 = make_float2(acc[mt][nt][2], acc[mt][nt][3]);
            *(float2*)(baseo + (size_t)oc0 * IMGPIX)       = v0;
            *(float2*)(baseo + (size_t)(oc0 + 8) * IMGPIX) = v1;
        }
    }
}

extern "C" void kernel_launch(void* const* d_in, const int* in_sizes, int n_in,
                              void* d_out, int out_size)
{
    const float* x = (const float*)d_in[0];
    const float* w = (const float*)d_in[1];
    float* out     = (float*)d_out;

    wprep_kernel<<<(OCTOT * KTOT + 255) / 256, 256>>>(w);
    xprep_kernel<<<(NIMG * XCH + 255) / 256, 256>>>(x);
    dim3 grid(NPIX / TILE_N, OCTOT / 128);         // (784, 2)
    conv_mma_kernel<<<grid, 256>>>(out);
}

// round 10
// speedup vs baseline: 2.1057x; 2.1057x over previous
#include <cuda_runtime.h>
#include <cstdint>

// Implicit-GEMM conv2d: mma.sync tf32, rs-major K ordering via prep kernels.
// Pre-pass: W -> g_wt[oc][rs*128+ci] tf32 ; x -> g_xt tf32 (RNA rounding).
// Main: CTA 128oc x 128pix, warps 2x4, warp tile 64x32, KC=16, 72 stages,
// double-buffered 40KB STATIC smem. Compute loop identical to the 704us R6
// kernel. Loader is synchronous LDG/STS (no cp.async, no attribute calls).
// [Resubmission of R9: failure pattern across rounds shows content-independent
//  container flake; every construct here passed individually in R6/R7.]

#define NIMG   32
#define CIN    128
#define HWDIM  56
#define OCTOT  256
#define IMGPIX 3136
#define XCH    (CIN*IMGPIX)
#define KTOT   1152
#define NPIX   (NIMG*IMGPIX)
#define KC     16
#define NSTEP  (KTOT/KC)      // 72
#define TILE_N 128
#define LDT    20             // smem row stride (floats): fragment-conflict-free
#define TSZ    (128*LDT)

__device__ uint32_t g_xt[NIMG * XCH];     // x as tf32 bits
__device__ uint32_t g_wt[OCTOT * KTOT];   // W reordered [oc][rs*128+ci], tf32

__device__ __forceinline__ uint32_t cvt_tf32(float f) {
    uint32_t r;
    asm("cvt.rna.tf32.f32 %0, %1;" : "=r"(r) : "f"(f));
    return r;
}
__device__ __forceinline__ void mma8(float* c, const uint32_t* a, const uint32_t* b) {
    asm volatile(
        "mma.sync.aligned.m16n8k8.row.col.f32.tf32.tf32.f32 "
        "{%0,%1,%2,%3}, {%4,%5,%6,%7}, {%8,%9}, {%0,%1,%2,%3};"
        : "+f"(c[0]), "+f"(c[1]), "+f"(c[2]), "+f"(c[3])
        : "r"(a[0]), "r"(a[1]), "r"(a[2]), "r"(a[3]), "r"(b[0]), "r"(b[1]));
}

// ---------------- pre-pass kernels ----------------
__global__ void wprep_kernel(const float* __restrict__ w) {
    int i = blockIdx.x * 256 + threadIdx.x;
    if (i < OCTOT * KTOT) {
        int oc = i / KTOT;
        int kk = i - oc * KTOT;          // rs*128 + ci
        int rs = kk >> 7;
        int ci = kk & 127;
        g_wt[i] = cvt_tf32(w[oc * KTOT + ci * 9 + rs]);
    }
}
__global__ void xprep_kernel(const float* __restrict__ x) {
    int i = blockIdx.x * 256 + threadIdx.x;
    if (i < NIMG * XCH) g_xt[i] = cvt_tf32(x[i]);
}

// ---------------- main kernel ----------------
__global__ __launch_bounds__(256, 2)
void conv_mma_kernel(float* __restrict__ out)
{
    __shared__ uint32_t smem[4 * TSZ];            // A0 A1 B0 B1 = 40 KB
    uint32_t* const As0 = smem;
    uint32_t* const As1 = smem + TSZ;
    uint32_t* const Bs0 = smem + 2 * TSZ;
    uint32_t* const Bs1 = smem + 3 * TSZ;

    const int tid  = threadIdx.x;
    const int lane = tid & 31;
    const int warp = tid >> 5;
    const int wm   = warp >> 2;
    const int wn   = warp & 3;
    const int g    = lane >> 2;
    const int tig  = lane & 3;

    const int tileBase = blockIdx.x * TILE_N;
    const int ocBase   = blockIdx.y * 128;

    // B-load mapping: thread -> (local pixel, k-half)
    const int pl = tid & 127;
    const int kh = tid >> 7;                      // 0/1 -> ci offset 8*kh
    const int P  = tileBase + pl;
    const int n_img = P / IMGPIX;
    const int q  = P - n_img * IMGPIX;
    const int hh = q / HWDIM;
    const int ww = q - hh * HWDIM;
    const uint32_t* xb = g_xt + (size_t)n_img * XCH + hh * HWDIM + ww;

    // A-load mapping (loop-invariant parts)
    const int a_oc = tid >> 2;                    // oc 0..63 (+64 on 2nd item)
    const int a_kq = tid & 3;
    const uint32_t* wA = g_wt + (size_t)(ocBase + a_oc) * KTOT + a_kq * 4;

    float acc[4][4][4];
#pragma unroll
    for (int i = 0; i < 4; i++)
#pragma unroll
        for (int j = 0; j < 4; j++)
#pragma unroll
            for (int k2 = 0; k2 < 4; k2++) acc[i][j][k2] = 0.f;

    // ---- stage loader: stage s -> rs = s>>3, ci base = (s&7)*16 ----
    auto load_stage = [&](uint32_t* Ad, uint32_t* Bd, int s) {
        const int rs  = s >> 3;
        const int cib = (s & 7) * 16;
        // A: 128 oc x 16 ci; 2x (LDG.128 -> STS.128) per thread
        const uint32_t* wsrc = wA + rs * 128 + cib;
        uint4 va0 = *(const uint4*)(wsrc);
        uint4 va1 = *(const uint4*)(wsrc + 64 * KTOT);
        uint32_t* ad0 = Ad + a_oc * LDT + a_kq * 4;
        *(uint4*)ad0              = va0;
        *(uint4*)(ad0 + 64 * LDT) = va1;
        // B: 8 coalesced LDG.32 under one uniform per-stage predicate
        const int r3 = rs / 3;
        const int dr = r3 - 1;
        const int ds = rs - r3 * 3 - 1;
        const bool in = ((unsigned)(hh + dr) < HWDIM) && ((unsigned)(ww + ds) < HWDIM);
        const uint32_t* xp = xb + (cib + kh * 8) * IMGPIX + dr * HWDIM + ds;
        uint4 vb0, vb1;
        vb0.x = in ? xp[0 * IMGPIX] : 0u;
        vb0.y = in ? xp[1 * IMGPIX] : 0u;
        vb0.z = in ? xp[2 * IMGPIX] : 0u;
        vb0.w = in ? xp[3 * IMGPIX] : 0u;
        vb1.x = in ? xp[4 * IMGPIX] : 0u;
        vb1.y = in ? xp[5 * IMGPIX] : 0u;
        vb1.z = in ? xp[6 * IMGPIX] : 0u;
        vb1.w = in ? xp[7 * IMGPIX] : 0u;
        uint32_t* bd = Bd + pl * LDT + kh * 8;    // 16B aligned: 80*pl + 32*kh
        *(uint4*)bd       = vb0;
        *(uint4*)(bd + 4) = vb1;
    };

    load_stage(As0, Bs0, 0);
    __syncthreads();

    for (int s = 0; s < NSTEP; s++) {
        const int cur = s & 1;
        const uint32_t* A = cur ? As1 : As0;
        const uint32_t* B = cur ? Bs1 : Bs0;
        if (s + 1 < NSTEP)
            load_stage(cur ? As0 : As1, cur ? Bs0 : Bs1, s + 1);

#pragma unroll
        for (int ks = 0; ks < 2; ks++) {
            uint32_t a[4][4], b[4][2];
#pragma unroll
            for (int mt = 0; mt < 4; mt++) {
                const uint32_t* ap = A + (wm * 64 + mt * 16 + g) * LDT + ks * 8 + tig;
                a[mt][0] = ap[0];
                a[mt][1] = ap[8 * LDT];
                a[mt][2] = ap[4];
                a[mt][3] = ap[8 * LDT + 4];
            }
#pragma unroll
            for (int nt = 0; nt < 4; nt++) {
                const uint32_t* bp = B + (wn * 32 + nt * 8 + g) * LDT + ks * 8 + tig;
                b[nt][0] = bp[0];
                b[nt][1] = bp[4];
            }
#pragma unroll
            for (int mt = 0; mt < 4; mt++)
#pragma unroll
                for (int nt = 0; nt < 4; nt++)
                    mma8(acc[mt][nt], a[mt], b[nt]);
        }
        __syncthreads();
    }

    // ---- epilogue: direct STG.64 (c0,c1 adjacent pixels) ----
#pragma unroll
    for (int nt = 0; nt < 4; nt++) {
        int Pp = tileBase + wn * 32 + nt * 8 + 2 * tig;
        int n2 = Pp / IMGPIX;
        int rm = Pp - n2 * IMGPIX;
        float* baseo = out + ((size_t)n2 * OCTOT + ocBase) * IMGPIX + rm;
#pragma unroll
        for (int mt = 0; mt < 4; mt++) {
            int oc0 = wm * 64 + mt * 16 + g;
            float2 v0 = make_float2(acc[mt][nt][0], acc[mt][nt][1]);
            float2 v1 = make_float2(acc[mt][nt][2], acc[mt][nt][3]);
            *(float2*)(baseo + (size_t)oc0 * IMGPIX)       = v0;
            *(float2*)(baseo + (size_t)(oc0 + 8) * IMGPIX) = v1;
        }
    }
}

extern "C" void kernel_launch(void* const* d_in, const int* in_sizes, int n_in,
                              void* d_out, int out_size)
{
    const float* x = (const float*)d_in[0];
    const float* w = (const float*)d_in[1];
    float* out     = (float*)d_out;

    wprep_kernel<<<(OCTOT * KTOT + 255) / 256, 256>>>(w);
    xprep_kernel<<<(NIMG * XCH + 255) / 256, 256>>>(x);
    dim3 grid(NPIX / TILE_N, OCTOT / 128);         // (784, 2)
    conv_mma_kernel<<<grid, 256>>>(out);
}